// round 12
// baseline (speedup 1.0000x reference)
#include <cuda_runtime.h>
#include <math.h>

#define BG 256
#define TT 64
#define PP 10
#define DD 128
#define HH 64
#define BT (BG*TT)   // 16384

typedef unsigned long long u64;

// ---- device scratch (allocation-free) ----
__device__ float g_z[BT*PP*64];            // SGCN output z  [bt][p][64]
__device__ float g_gih[(size_t)BT*PP*256]; // gates_ih+bias  [bt][p][256]
// k-quad interleaved weights: float4 = (W[4kq..4kq+3][col]) ; lane dim = col
__device__ float4 g_WbQ[2*64*32];          // base [s][kq][col]
__device__ float4 g_WdQ[2*2*56*32];        // deep [s][layer][kq][col]
__device__ float4 g_WihQ[PP*16*256];       // lstm-ih [p][iq][g]

// ---- packed fp32x2 helpers ----
__device__ __forceinline__ void ffma2(u64& d, u64 a, u64 b){
    asm("fma.rn.f32x2 %0, %1, %2, %0;" : "+l"(d) : "l"(a), "l"(b));
}
__device__ __forceinline__ float hadd2(u64 v){
    float lo, hi; asm("mov.b64 {%0,%1}, %2;" : "=f"(lo), "=f"(hi) : "l"(v));
    return lo + hi;
}

// fast activations
__device__ __forceinline__ float tanh_mufu(float x){
    float y; asm("tanh.approx.f32 %0, %1;" : "=f"(y) : "f"(x)); return y;
}
__device__ __forceinline__ float sigmoid_fast(float v){
    return __fdividef(1.0f, 1.0f + __expf(-v));
}
__device__ __forceinline__ float tanh_fast(float v){
    return __fdividef(2.0f, 1.0f + __expf(-2.0f*v)) - 1.0f;
}

// ------------------------------------------------------------------
// Kernel 0: weight re-layout (k-quad interleave, col-coalesced)
// ------------------------------------------------------------------
__global__ void transform_weights(
    const float* __restrict__ Wpb, const float* __restrict__ Wnb,
    const float* __restrict__ Wpd, const float* __restrict__ Wnd,
    const float* __restrict__ Wih)
{
    int idx = blockIdx.x*blockDim.x + threadIdx.x;
    if (idx < 2*64*32){
        int s = idx / 2048, rem = idx - s*2048;
        int kq = rem >> 5, col = rem & 31;
        const float* W = s ? Wnb : Wpb;          // [256][32]
        g_WbQ[idx] = make_float4(W[(4*kq+0)*32+col], W[(4*kq+1)*32+col],
                                 W[(4*kq+2)*32+col], W[(4*kq+3)*32+col]);
    } else if (idx < 2*64*32 + 2*2*56*32){
        int i2 = idx - 2*64*32;
        int s = i2 / 3584; int rem = i2 - s*3584;
        int layer = rem / 1792; rem -= layer*1792;
        int kq = rem >> 5, col = rem & 31;
        const float* W = (s ? Wnd : Wpd) + layer*224*32;   // [224][32]
        g_WdQ[i2] = make_float4(W[(4*kq+0)*32+col], W[(4*kq+1)*32+col],
                                W[(4*kq+2)*32+col], W[(4*kq+3)*32+col]);
    } else if (idx < 2*64*32 + 2*2*56*32 + PP*16*256){
        int i3 = idx - (2*64*32 + 2*2*56*32);
        int p = i3 / 4096; int rem = i3 - p*4096;
        int iq = rem >> 8, g = rem & 255;
        const float* W = Wih + (size_t)p*16384 + g*64;     // row g, 64 i
        g_WihQ[i3] = make_float4(W[4*iq+0], W[4*iq+1], W[4*iq+2], W[4*iq+3]);
    }
}

// ------------------------------------------------------------------
// Kernel 1: SGCN. TWO (b,t) tiles per block for ILP; 256 threads.
// grid = BT/2 = 8192.
// ------------------------------------------------------------------
__global__ __launch_bounds__(256) void sgcn_kernel(
    const float* __restrict__ x,
    const float* __restrict__ Apos, const float* __restrict__ Aneg,
    const float* __restrict__ bpb,  const float* __restrict__ bnb,
    const float* __restrict__ bpd,  const float* __restrict__ bnd)
{
    __shared__ __align__(16) float xs[2][PP*DD];       // 2x1280
    __shared__ float Asm[2][2][PP*PP];                 // [u][s][100]
    __shared__ float rs[2][2][PP];
    __shared__ __align__(16) float aggx[2][2*PP*DD];   // 2x2560
    __shared__ __align__(16) float cat[2][6*PP*32];    // 2x1920
    __shared__ float part[2][4*2*PP*32];               // 2x2560

    const int bt0 = blockIdx.x * 2;
    const int tid = threadIdx.x;

    {   // x tiles: 2560 floats contiguous
        const float4* x4 = (const float4*)(x + (size_t)bt0*PP*DD);
        float4* xs4 = (float4*)xs;
        for (int i = tid; i < 2*PP*DD/4; i += 256) xs4[i] = x4[i];
    }
    for (int o = tid; o < 400; o += 256){              // FIX: grid-stride (was if tid<400)
        int u = o/200; int r2 = o - u*200;
        int s = r2/100;  int j  = r2 - s*100;
        Asm[u][s][j] = (s ? Aneg : Apos)[(size_t)(bt0+u)*100 + j];
    }
    __syncthreads();
    if (tid < 40){
        int u = tid/20; int r2 = tid - u*20;
        int s = r2/10;  int r  = r2 - s*10;
        float sum = 0.f;
        #pragma unroll
        for (int j=0;j<10;j++) sum += Asm[u][s][r*10+j];
        rs[u][s][r] = __fdividef(1.0f, sum + 1e-8f);
    }
    __syncthreads();
    for (int o = tid; o < 400; o += 256){              // FIX: grid-stride
        int u = o/200; int r2 = o - u*200;
        int s = r2/100;  int j  = r2 - s*100;
        Asm[u][s][j] *= rs[u][s][j/10];
    }
    __syncthreads();

    // aggx[u][s][r][:] = An_s[r] @ x_u   (1280 float4 items)
    for (int o = tid; o < 2*2*PP*32; o += 256){
        int u = o / 640; int rem = o - u*640;
        int s = rem / 320; rem -= s*320;
        int r = rem >> 5; int d4 = rem & 31;
        const float4* xs4 = (const float4*)xs[u];
        float4 sum = make_float4(0.f,0.f,0.f,0.f);
        #pragma unroll
        for (int j=0;j<10;j++){
            float a = Asm[u][s][r*10+j];
            float4 xv = xs4[j*32 + d4];
            sum.x += a*xv.x; sum.y += a*xv.y; sum.z += a*xv.z; sum.w += a*xv.w;
        }
        ((float4*)aggx[u])[s*320 + r*32 + d4] = sum;
    }
    __syncthreads();

    // base matmul: K=256, FFMA2, weights shared across the 2 tiles
    {
        const int col = tid & 31;
        const int s   = (tid>>5) & 1;
        const int q   = tid>>6;          // 0..3 -> 64 k (16 quads) each
        const ulonglong2* Wq = (const ulonglong2*)g_WbQ + (s*64 + q*16)*32 + col;
        const float* src0 = (q < 2) ? (aggx[0] + s*1280 + q*64) : (xs[0] + (q-2)*64);
        const float* src1 = (q < 2) ? (aggx[1] + s*1280 + q*64) : (xs[1] + (q-2)*64);
        u64 accP[2][10];
        #pragma unroll
        for (int r=0;r<10;r++){ accP[0][r]=0ull; accP[1][r]=0ull; }
        #pragma unroll 2
        for (int kq=0;kq<16;kq++){
            ulonglong2 w = Wq[kq*32];
            #pragma unroll
            for (int r=0;r<10;r++){
                ulonglong2 a0 = *(const ulonglong2*)&src0[r*128 + kq*4];
                ulonglong2 a1 = *(const ulonglong2*)&src1[r*128 + kq*4];
                ffma2(accP[0][r], a0.x, w.x);
                ffma2(accP[1][r], a1.x, w.x);
                ffma2(accP[0][r], a0.y, w.y);
                ffma2(accP[1][r], a1.y, w.y);
            }
        }
        #pragma unroll
        for (int r=0;r<10;r++){
            part[0][((q*2+s)*10+r)*32+col] = hadd2(accP[0][r]);
            part[1][((q*2+s)*10+r)*32+col] = hadd2(accP[1][r]);
        }
    }
    __syncthreads();
    for (int o=tid; o<1280; o+=256){
        int u = o/640;
        int rem = o - u*640;
        int s = rem/320; rem -= s*320;
        int r = rem>>5, col = rem&31;
        float v = (s ? bnb : bpb)[col];
        #pragma unroll
        for (int q=0;q<4;q++) v += part[u][((q*2+s)*10+r)*32+col];
        cat[u][(4+s)*320 + r*32 + col] = tanh_mufu(v);
    }
    __syncthreads();

    // two deep layers, K=224, FFMA2
    for (int layer=0; layer<2; layer++){
        for (int o=tid; o<640; o+=256){
            int u = o/320; int rem = o - u*320;
            int m = rem/80; rem -= m*80;
            int r = rem>>3, c4 = (rem&7)*4;
            int as = m>>1, hsn = m&1;
            float4 sum = make_float4(0.f,0.f,0.f,0.f);
            #pragma unroll
            for (int j=0;j<10;j++){
                float a = Asm[u][as][r*10+j];
                float4 h = *(const float4*)&cat[u][(4+hsn)*320 + j*32 + c4];
                sum.x += a*h.x; sum.y += a*h.y; sum.z += a*h.z; sum.w += a*h.w;
            }
            *(float4*)&cat[u][m*320 + r*32 + c4] = sum;
        }
        __syncthreads();
        {
            const int col = tid & 31;
            const int s   = (tid>>5) & 1;
            const int q   = tid>>6;      // 0..3 -> 56 k (14 quads) each
            const ulonglong2* Wq = (const ulonglong2*)g_WdQ
                                 + (((s*2+layer)*56) + q*14)*32 + col;
            u64 accP[2][10];
            #pragma unroll
            for (int r=0;r<10;r++){ accP[0][r]=0ull; accP[1][r]=0ull; }
            #pragma unroll 2
            for (int kq=0;kq<14;kq++){
                int k = q*56 + kq*4;
                int blk = k>>5, ko = k&31;
                int boff = ((blk<6) ? blk : (4+s))*320 + ko;
                const float* s0 = cat[0] + boff;
                const float* s1 = cat[1] + boff;
                ulonglong2 w = Wq[kq*32];
                #pragma unroll
                for (int r=0;r<10;r++){
                    ulonglong2 a0 = *(const ulonglong2*)&s0[r*32];
                    ulonglong2 a1 = *(const ulonglong2*)&s1[r*32];
                    ffma2(accP[0][r], a0.x, w.x);
                    ffma2(accP[1][r], a1.x, w.x);
                    ffma2(accP[0][r], a0.y, w.y);
                    ffma2(accP[1][r], a1.y, w.y);
                }
            }
            #pragma unroll
            for (int r=0;r<10;r++){
                part[0][((q*2+s)*10+r)*32+col] = hadd2(accP[0][r]);
                part[1][((q*2+s)*10+r)*32+col] = hadd2(accP[1][r]);
            }
        }
        __syncthreads();
        for (int o=tid; o<1280; o+=256){
            int u = o/640; int rem = o - u*640;
            int s = rem/320; rem -= s*320;
            int r = rem>>5, col = rem&31;
            float v = (s ? bnd : bpd)[layer*32+col];
            #pragma unroll
            for (int q=0;q<4;q++) v += part[u][((q*2+s)*10+r)*32+col];
            cat[u][(4+s)*320 + r*32 + col] = tanh_mufu(v);
        }
        __syncthreads();
    }

    // write z for both tiles
    for (int o=tid; o<1280; o+=256){
        int u = o/640; int rem = o - u*640;
        int r = rem>>6, c = rem&63, s = c>>5, cc = c&31;
        g_z[(size_t)(bt0+u)*PP*64 + rem] = cat[u][(4+s)*320 + r*32 + cc];
    }
}

// ------------------------------------------------------------------
// Kernel 2: gates_ih = z @ W_ih^T + (b_ih + b_hh)  (exact R5 version)
// thread = gate g, 16 bt-rows per block. grid: (BT/16, PP)
// ------------------------------------------------------------------
__global__ __launch_bounds__(256) void gih_kernel(
    const float* __restrict__ bih, const float* __restrict__ bhh)
{
    __shared__ __align__(16) float zs[16*64];

    const int p   = blockIdx.y;
    const int r0  = blockIdx.x * 16;
    const int g   = threadIdx.x;    // gate 0..255

    {   // one float4 per thread
        int rr = g >> 4, d4 = g & 15;
        ((float4*)zs)[g] = *(const float4*)&g_z[((size_t)(r0+rr)*10 + p)*64 + d4*4];
    }
    __syncthreads();

    const ulonglong2* Wq = (const ulonglong2*)g_WihQ + p*4096 + g;  // [iq][g] stride 256

    u64 accP[16];
    #pragma unroll
    for (int r=0;r<16;r++) accP[r]=0ull;

    #pragma unroll 4
    for (int iq=0; iq<16; iq++){
        ulonglong2 w = Wq[iq*256];
        #pragma unroll
        for (int r=0;r<16;r++){
            ulonglong2 z2 = *(const ulonglong2*)&zs[r*64 + iq*4];
            ffma2(accP[r], z2.x, w.x);
            ffma2(accP[r], z2.y, w.y);
        }
    }

    float bsum = bih[p*256+g] + bhh[p*256+g];
    #pragma unroll
    for (int r=0;r<16;r++){
        g_gih[((size_t)(r0+r)*10 + p)*256 + g] = hadd2(accP[r]) + bsum;
    }
}

// ------------------------------------------------------------------
// Kernel 3: LSTM recurrence (exact Round-3 version, known 233us).
// One block per (p, 4-game chunk). grid = 640.
// ------------------------------------------------------------------
__global__ __launch_bounds__(256) void lstm_kernel(
    const float* __restrict__ Whh, float* __restrict__ out)
{
    __shared__ float hs[4][64];
    __shared__ float gsm[4][256];

    const int p     = blockIdx.x >> 6;
    const int chunk = blockIdx.x & 63;
    const int b0    = chunk*4;
    const int gt    = threadIdx.x;
    const int gm    = gt >> 6;
    const int j     = gt & 63;

    float wreg[64];
    {
        const float* Wp = Whh + (size_t)p*16384 + gt*64;
        #pragma unroll
        for (int k=0;k<64;k+=4){
            float4 w4 = *(const float4*)&Wp[k];
            wreg[k+0]=w4.x; wreg[k+1]=w4.y; wreg[k+2]=w4.z; wreg[k+3]=w4.w;
        }
    }
    ((float*)hs)[gt] = 0.f;
    float creg = 0.f;
    __syncthreads();

    float pf[4];
    #pragma unroll
    for (int g4=0; g4<4; g4++)
        pf[g4] = g_gih[((size_t)(b0+g4)*64*10 + p)*256 + gt];

    for (int t=0; t<TT; t++){
        float acc0 = pf[0], acc1 = pf[1], acc2 = pf[2], acc3 = pf[3];
        #pragma unroll
        for (int k0=0;k0<64;k0+=4){
            float4 h0 = *(const float4*)&hs[0][k0];
            float4 h1 = *(const float4*)&hs[1][k0];
            float4 h2 = *(const float4*)&hs[2][k0];
            float4 h3 = *(const float4*)&hs[3][k0];
            float w0 = wreg[k0], w1 = wreg[k0+1], w2 = wreg[k0+2], w3 = wreg[k0+3];
            acc0 += w0*h0.x + w1*h0.y + w2*h0.z + w3*h0.w;
            acc1 += w0*h1.x + w1*h1.y + w2*h1.z + w3*h1.w;
            acc2 += w0*h2.x + w1*h2.y + w2*h2.z + w3*h2.w;
            acc3 += w0*h3.x + w1*h3.y + w2*h3.z + w3*h3.w;
        }
        if (t < TT-1){
            #pragma unroll
            for (int g4=0; g4<4; g4++)
                pf[g4] = g_gih[(((size_t)(b0+g4)*64 + t+1)*10 + p)*256 + gt];
        }
        gsm[0][gt] = acc0; gsm[1][gt] = acc1; gsm[2][gt] = acc2; gsm[3][gt] = acc3;
        __syncthreads();
        {
            float ig = sigmoid_fast(gsm[gm][j]);
            float fg = sigmoid_fast(gsm[gm][64+j]);
            float gg = tanh_fast   (gsm[gm][128+j]);
            float og = sigmoid_fast(gsm[gm][192+j]);
            creg = fg*creg + ig*gg;
            float h = og*tanh_fast(creg);
            hs[gm][j] = h;
            size_t bt = (size_t)(b0+gm)*64 + t;
            out[(bt*10 + p)*64 + j] = h;
        }
        __syncthreads();
    }
}

// ------------------------------------------------------------------
extern "C" void kernel_launch(void* const* d_in, const int* in_sizes, int n_in,
                              void* d_out, int out_size)
{
    const float* x    = (const float*)d_in[0];
    const float* Apos = (const float*)d_in[1];
    const float* Aneg = (const float*)d_in[2];
    const float* Wpb  = (const float*)d_in[3];
    const float* bpb  = (const float*)d_in[4];
    const float* Wnb  = (const float*)d_in[5];
    const float* bnb  = (const float*)d_in[6];
    const float* Wpd  = (const float*)d_in[7];
    const float* bpd  = (const float*)d_in[8];
    const float* Wnd  = (const float*)d_in[9];
    const float* bnd  = (const float*)d_in[10];
    const float* Wih  = (const float*)d_in[11];
    const float* Whh  = (const float*)d_in[12];
    const float* bih  = (const float*)d_in[13];
    const float* bhh  = (const float*)d_in[14];
    float* out = (float*)d_out;

    const int nW = 2*64*32 + 2*2*56*32 + PP*16*256;
    transform_weights<<<(nW + 255)/256, 256>>>(Wpb, Wnb, Wpd, Wnd, Wih);

    sgcn_kernel<<<BT/2, 256>>>(x, Apos, Aneg, bpb, bnb, bpd, bnd);

    dim3 gg(BT/16, PP);
    gih_kernel<<<gg, 256>>>(bih, bhh);

    lstm_kernel<<<PP*(BG/4), 256>>>(Whh, out);   // 640 blocks
}

// round 14
// speedup vs baseline: 1.2862x; 1.2862x over previous
#include <cuda_runtime.h>
#include <math.h>

#define BG 256
#define TT 64
#define PP 10
#define DD 128
#define HH 64
#define BT (BG*TT)   // 16384

typedef unsigned long long u64;

// ---- device scratch (allocation-free) ----
__device__ float g_z[BT*PP*64];            // SGCN output z  [bt][p][64]
__device__ float g_gih[(size_t)BT*PP*256]; // gates_ih+bias  [bt][p][256]
__device__ float4 g_WbF[4096];             // base W tf32 frags [s][q][kf][fp][lane] (2*4*8*2*32)
__device__ float4 g_WdF[7168];             // deep W tf32 frags [s][layer][q][kf][fp][lane] (2*2*4*7*2*32)
__device__ float4 g_WihQ[PP*16*256];       // lstm-ih [p][iq][g]

// ---- packed fp32x2 helpers (gih) ----
__device__ __forceinline__ void ffma2(u64& d, u64 a, u64 b){
    asm("fma.rn.f32x2 %0, %1, %2, %0;" : "+l"(d) : "l"(a), "l"(b));
}
__device__ __forceinline__ float hadd2(u64 v){
    float lo, hi; asm("mov.b64 {%0,%1}, %2;" : "=f"(lo), "=f"(hi) : "l"(v));
    return lo + hi;
}

// ---- tf32 helpers ----
__device__ __forceinline__ float to_tf32(float x){
    float y; asm("cvt.rna.tf32.f32 %0, %1;" : "=f"(y) : "f"(x)); return y;
}
// D = A(16x8,row) * B(8x8,col) + D, tf32 inputs, f32 accum
__device__ __forceinline__ void mma_tf32(float* c, const float* a, float b0, float b1){
    const unsigned* A = (const unsigned*)a;
    unsigned B0 = __float_as_uint(b0), B1 = __float_as_uint(b1);
    asm volatile(
        "mma.sync.aligned.m16n8k8.row.col.f32.tf32.tf32.f32 "
        "{%0,%1,%2,%3}, {%4,%5,%6,%7}, {%8,%9}, {%0,%1,%2,%3};\n"
        : "+f"(c[0]), "+f"(c[1]), "+f"(c[2]), "+f"(c[3])
        : "r"(A[0]), "r"(A[1]), "r"(A[2]), "r"(A[3]), "r"(B0), "r"(B1));
}

// fast activations
__device__ __forceinline__ float tanh_mufu(float x){
    float y; asm("tanh.approx.f32 %0, %1;" : "=f"(y) : "f"(x)); return y;
}
__device__ __forceinline__ float sigmoid_fast(float v){
    return __fdividef(1.0f, 1.0f + __expf(-v));
}
__device__ __forceinline__ float tanh_fast(float v){
    return __fdividef(2.0f, 1.0f + __expf(-2.0f*v)) - 1.0f;
}

// ------------------------------------------------------------------
// Kernel 0: weight packing. Base/deep -> tf32 mma B-fragments;
// W_ih -> k-quad layout for gih.
// ------------------------------------------------------------------
__global__ void transform_weights(
    const float* __restrict__ Wpb, const float* __restrict__ Wnb,
    const float* __restrict__ Wpd, const float* __restrict__ Wnd,
    const float* __restrict__ Wih)
{
    int idx = blockIdx.x*blockDim.x + threadIdx.x;
    if (idx < 4096){
        // base B frags: [s][q][kf][fp][lane]   (s:1b q:2b kf:3b fp:1b lane:5b)
        int lane = idx & 31; int t = idx >> 5;
        int fp = t & 1; t >>= 1;
        int kf = t & 7; t >>= 3;
        int q  = t & 3; int s = t >> 2;
        const float* W = s ? Wnb : Wpb;           // [256][32]
        int kb = q*64 + kf*8 + (lane & 3);
        int n0 = lane >> 2;
        int f0 = fp*2, f1 = fp*2 + 1;
        g_WbF[idx] = make_float4(
            to_tf32(W[(kb  )*32 + f0*8 + n0]), to_tf32(W[(kb+4)*32 + f0*8 + n0]),
            to_tf32(W[(kb  )*32 + f1*8 + n0]), to_tf32(W[(kb+4)*32 + f1*8 + n0]));
    } else if (idx < 4096 + 7168){
        // deep B frags: [s][layer][q][kf][fp][lane]
        int i2 = idx - 4096;
        int lane = i2 & 31; int t = i2 >> 5;
        int fp = t & 1; t >>= 1;
        int kf = t % 7; t /= 7;
        int q  = t & 3; t >>= 2;
        int layer = t & 1; int s = t >> 1;
        const float* W = (s ? Wnd : Wpd) + layer*224*32;   // [224][32]
        int kb = q*56 + kf*8 + (lane & 3);
        int n0 = lane >> 2;
        int f0 = fp*2, f1 = fp*2 + 1;
        g_WdF[i2] = make_float4(
            to_tf32(W[(kb  )*32 + f0*8 + n0]), to_tf32(W[(kb+4)*32 + f0*8 + n0]),
            to_tf32(W[(kb  )*32 + f1*8 + n0]), to_tf32(W[(kb+4)*32 + f1*8 + n0]));
    } else if (idx < 4096 + 7168 + PP*16*256){
        int i3 = idx - (4096 + 7168);
        int p = i3 / 4096; int rem = i3 - p*4096;
        int iq = rem >> 8, g = rem & 255;
        const float* W = Wih + (size_t)p*16384 + g*64;     // row g, 64 i
        g_WihQ[i3] = make_float4(W[4*iq+0], W[4*iq+1], W[4*iq+2], W[4*iq+3]);
    }
}

// ------------------------------------------------------------------
// Kernel 1: SGCN. One block per (b,t). 256 threads = 8 warps.
// Matmuls on tensor cores (tf32 mma), warp = (sign, k-slice).
// ------------------------------------------------------------------
__global__ __launch_bounds__(256) void sgcn_kernel(
    const float* __restrict__ x,
    const float* __restrict__ Apos, const float* __restrict__ Aneg,
    const float* __restrict__ bpb,  const float* __restrict__ bnb,
    const float* __restrict__ bpd,  const float* __restrict__ bnd)
{
    __shared__ __align__(16) float xs[PP*DD];        // 1280
    __shared__ float Asm[2][PP*PP];
    __shared__ float rs[2][PP];
    __shared__ __align__(16) float aggx[2*PP*DD];    // 2560
    __shared__ __align__(16) float cat[6*PP*32];     // [0..3]=aggs, [4]=h_pos, [5]=h_neg
    __shared__ float part[4*2*PP*32];                // 2560

    const int bt  = blockIdx.x;
    const int tid = threadIdx.x;
    const int w   = tid >> 5;       // warp 0..7
    const int l   = tid & 31;
    const int s   = w & 1;          // sign
    const int q   = w >> 1;         // k-slice 0..3
    const int gid = l >> 2;         // 0..7
    const int tig = l & 3;          // 0..3

    {   // x tile
        const float4* x4 = (const float4*)(x + (size_t)bt*PP*DD);
        float4* xs4 = (float4*)xs;
        for (int i = tid; i < PP*DD/4; i += 256) xs4[i] = x4[i];
    }
    if (tid < 200){
        int ss = tid/100, idx = tid - ss*100;
        Asm[ss][idx] = (ss ? Aneg : Apos)[(size_t)bt*100 + idx];
    }
    __syncthreads();
    if (tid < 20){
        int ss = tid/10, r = tid - ss*10;
        float sum = 0.f;
        #pragma unroll
        for (int j=0;j<10;j++) sum += Asm[ss][r*10+j];
        rs[ss][r] = __fdividef(1.0f, sum + 1e-8f);
    }
    __syncthreads();
    if (tid < 200){
        int ss = tid/100, idx = tid - ss*100;
        Asm[ss][idx] *= rs[ss][idx/10];
    }
    __syncthreads();

    // aggx[s][r][:] = An_s[r] @ x
    {
        float4* ag4 = (float4*)aggx;
        const float4* xs4 = (const float4*)xs;
        for (int o = tid; o < 2*PP*32; o += 256){
            int ss = o / 320; int rem = o - ss*320;
            int r = rem >> 5; int d4 = rem & 31;
            float4 sum = make_float4(0.f,0.f,0.f,0.f);
            #pragma unroll
            for (int j=0;j<10;j++){
                float a = Asm[ss][r*10+j];
                float4 xv = xs4[j*32 + d4];
                sum.x += a*xv.x; sum.y += a*xv.y; sum.z += a*xv.z; sum.w += a*xv.w;
            }
            ag4[o] = sum;
        }
    }
    __syncthreads();

    // ---- base matmul on tensor cores: per warp M=16(10), N=32, K=64 ----
    {
        const float* src = (q < 2) ? (aggx + s*1280 + q*64) : (xs + (q-2)*64);
        float a[8][4];
        #pragma unroll
        for (int kf=0; kf<8; kf++){
            int c0 = kf*8 + tig;
            a[kf][0] = to_tf32(src[gid*128 + c0]);
            a[kf][1] = (gid<2) ? to_tf32(src[(gid+8)*128 + c0]) : 0.f;
            a[kf][2] = to_tf32(src[gid*128 + c0 + 4]);
            a[kf][3] = (gid<2) ? to_tf32(src[(gid+8)*128 + c0 + 4]) : 0.f;
        }
        float acc[4][4];
        #pragma unroll
        for (int f=0; f<4; f++){
            #pragma unroll
            for (int e=0; e<4; e++) acc[f][e] = 0.f;
        }
        const float4* BF = g_WbF + (size_t)((s*4+q)*8)*2*32;
        #pragma unroll
        for (int kf=0; kf<8; kf++){
            float4 b01 = BF[(kf*2+0)*32 + l];
            float4 b23 = BF[(kf*2+1)*32 + l];
            mma_tf32(acc[0], a[kf], b01.x, b01.y);
            mma_tf32(acc[1], a[kf], b01.z, b01.w);
            mma_tf32(acc[2], a[kf], b23.x, b23.y);
            mma_tf32(acc[3], a[kf], b23.z, b23.w);
        }
        float* pp = part + ((q*2+s)*10)*32;
        #pragma unroll
        for (int f=0; f<4; f++){
            int n0 = f*8 + tig*2;
            pp[gid*32 + n0]     = acc[f][0];
            pp[gid*32 + n0 + 1] = acc[f][1];
            if (gid < 2){
                pp[(gid+8)*32 + n0]     = acc[f][2];
                pp[(gid+8)*32 + n0 + 1] = acc[f][3];
            }
        }
    }
    __syncthreads();
    for (int o=tid; o<640; o+=256){
        int ss = o/320, rem = o - ss*320, r = rem>>5, col = rem&31;
        float v = (ss ? bnb : bpb)[col];
        #pragma unroll
        for (int qq=0;qq<4;qq++) v += part[((qq*2+ss)*10+r)*32+col];
        cat[(4+ss)*320 + r*32 + col] = tanh_mufu(v);
    }
    __syncthreads();

    // ---- two deep layers: per warp M=16(10), N=32, K=56 ----
    for (int layer=0; layer<2; layer++){
        for (int o=tid; o<320; o+=256){
            int m = o/80, rem = o - m*80, r = rem>>3, c4 = (rem&7)*4;
            int as = m>>1, hsn = m&1;
            float4 sum = make_float4(0.f,0.f,0.f,0.f);
            #pragma unroll
            for (int j=0;j<10;j++){
                float a = Asm[as][r*10+j];
                float4 h = *(const float4*)&cat[(4+hsn)*320 + j*32 + c4];
                sum.x += a*h.x; sum.y += a*h.y; sum.z += a*h.z; sum.w += a*h.w;
            }
            *(float4*)&cat[m*320 + r*32 + c4] = sum;
        }
        __syncthreads();
        {
            float a[7][4];
            #pragma unroll
            for (int kf=0; kf<7; kf++){
                int k0 = q*56 + kf*8;
                int blk = k0 >> 5, ko = k0 & 31;
                const float* srcp = cat + ((blk<6) ? blk : (4+s))*320;
                int c0 = ko + tig;
                a[kf][0] = to_tf32(srcp[gid*32 + c0]);
                a[kf][1] = (gid<2) ? to_tf32(srcp[(gid+8)*32 + c0]) : 0.f;
                a[kf][2] = to_tf32(srcp[gid*32 + c0 + 4]);
                a[kf][3] = (gid<2) ? to_tf32(srcp[(gid+8)*32 + c0 + 4]) : 0.f;
            }
            float acc[4][4];
            #pragma unroll
            for (int f=0; f<4; f++){
                #pragma unroll
                for (int e=0; e<4; e++) acc[f][e] = 0.f;
            }
            const float4* BF = g_WdF + (size_t)(((s*2+layer)*4 + q)*7)*2*32;
            #pragma unroll
            for (int kf=0; kf<7; kf++){
                float4 b01 = BF[(kf*2+0)*32 + l];
                float4 b23 = BF[(kf*2+1)*32 + l];
                mma_tf32(acc[0], a[kf], b01.x, b01.y);
                mma_tf32(acc[1], a[kf], b01.z, b01.w);
                mma_tf32(acc[2], a[kf], b23.x, b23.y);
                mma_tf32(acc[3], a[kf], b23.z, b23.w);
            }
            float* pp = part + ((q*2+s)*10)*32;
            #pragma unroll
            for (int f=0; f<4; f++){
                int n0 = f*8 + tig*2;
                pp[gid*32 + n0]     = acc[f][0];
                pp[gid*32 + n0 + 1] = acc[f][1];
                if (gid < 2){
                    pp[(gid+8)*32 + n0]     = acc[f][2];
                    pp[(gid+8)*32 + n0 + 1] = acc[f][3];
                }
            }
        }
        __syncthreads();
        for (int o=tid; o<640; o+=256){
            int ss = o/320, rem = o - ss*320, r = rem>>5, col = rem&31;
            float v = (ss ? bnd : bpd)[layer*32+col];
            #pragma unroll
            for (int qq=0;qq<4;qq++) v += part[((qq*2+ss)*10+r)*32+col];
            cat[(4+ss)*320 + r*32 + col] = tanh_mufu(v);
        }
        __syncthreads();
    }

    // write z
    float* zo = g_z + (size_t)bt*PP*64;
    for (int o=tid; o<640; o+=256){
        int r = o>>6, c = o&63, ss = c>>5, cc = c&31;
        zo[o] = cat[(4+ss)*320 + r*32 + cc];
    }
}

// ------------------------------------------------------------------
// Kernel 2: gates_ih = z @ W_ih^T + (b_ih + b_hh)  (exact R5 version)
// thread = gate g, 16 bt-rows per block. grid: (BT/16, PP)
// ------------------------------------------------------------------
__global__ __launch_bounds__(256) void gih_kernel(
    const float* __restrict__ bih, const float* __restrict__ bhh)
{
    __shared__ __align__(16) float zs[16*64];

    const int p   = blockIdx.y;
    const int r0  = blockIdx.x * 16;
    const int g   = threadIdx.x;    // gate 0..255

    {   // one float4 per thread
        int rr = g >> 4, d4 = g & 15;
        ((float4*)zs)[g] = *(const float4*)&g_z[((size_t)(r0+rr)*10 + p)*64 + d4*4];
    }
    __syncthreads();

    const ulonglong2* Wq = (const ulonglong2*)g_WihQ + p*4096 + g;  // [iq][g] stride 256

    u64 accP[16];
    #pragma unroll
    for (int r=0;r<16;r++) accP[r]=0ull;

    #pragma unroll 4
    for (int iq=0; iq<16; iq++){
        ulonglong2 w = Wq[iq*256];
        #pragma unroll
        for (int r=0;r<16;r++){
            ulonglong2 z2 = *(const ulonglong2*)&zs[r*64 + iq*4];
            ffma2(accP[r], z2.x, w.x);
            ffma2(accP[r], z2.y, w.y);
        }
    }

    float bsum = bih[p*256+g] + bhh[p*256+g];
    #pragma unroll
    for (int r=0;r<16;r++){
        g_gih[((size_t)(r0+r)*10 + p)*256 + g] = hadd2(accP[r]) + bsum;
    }
}

// ------------------------------------------------------------------
// Kernel 3: LSTM recurrence (exact Round-3 version, known 233us).
// One block per (p, 4-game chunk). grid = 640.
// ------------------------------------------------------------------
__global__ __launch_bounds__(256) void lstm_kernel(
    const float* __restrict__ Whh, float* __restrict__ out)
{
    __shared__ float hs[4][64];
    __shared__ float gsm[4][256];

    const int p     = blockIdx.x >> 6;
    const int chunk = blockIdx.x & 63;
    const int b0    = chunk*4;
    const int gt    = threadIdx.x;
    const int gm    = gt >> 6;
    const int j     = gt & 63;

    float wreg[64];
    {
        const float* Wp = Whh + (size_t)p*16384 + gt*64;
        #pragma unroll
        for (int k=0;k<64;k+=4){
            float4 w4 = *(const float4*)&Wp[k];
            wreg[k+0]=w4.x; wreg[k+1]=w4.y; wreg[k+2]=w4.z; wreg[k+3]=w4.w;
        }
    }
    ((float*)hs)[gt] = 0.f;
    float creg = 0.f;
    __syncthreads();

    float pf[4];
    #pragma unroll
    for (int g4=0; g4<4; g4++)
        pf[g4] = g_gih[((size_t)(b0+g4)*64*10 + p)*256 + gt];

    for (int t=0; t<TT; t++){
        float acc0 = pf[0], acc1 = pf[1], acc2 = pf[2], acc3 = pf[3];
        #pragma unroll
        for (int k0=0;k0<64;k0+=4){
            float4 h0 = *(const float4*)&hs[0][k0];
            float4 h1 = *(const float4*)&hs[1][k0];
            float4 h2 = *(const float4*)&hs[2][k0];
            float4 h3 = *(const float4*)&hs[3][k0];
            float w0 = wreg[k0], w1 = wreg[k0+1], w2 = wreg[k0+2], w3 = wreg[k0+3];
            acc0 += w0*h0.x + w1*h0.y + w2*h0.z + w3*h0.w;
            acc1 += w0*h1.x + w1*h1.y + w2*h1.z + w3*h1.w;
            acc2 += w0*h2.x + w1*h2.y + w2*h2.z + w3*h2.w;
            acc3 += w0*h3.x + w1*h3.y + w2*h3.z + w3*h3.w;
        }
        if (t < TT-1){
            #pragma unroll
            for (int g4=0; g4<4; g4++)
                pf[g4] = g_gih[(((size_t)(b0+g4)*64 + t+1)*10 + p)*256 + gt];
        }
        gsm[0][gt] = acc0; gsm[1][gt] = acc1; gsm[2][gt] = acc2; gsm[3][gt] = acc3;
        __syncthreads();
        {
            float ig = sigmoid_fast(gsm[gm][j]);
            float fg = sigmoid_fast(gsm[gm][64+j]);
            float gg = tanh_fast   (gsm[gm][128+j]);
            float og = sigmoid_fast(gsm[gm][192+j]);
            creg = fg*creg + ig*gg;
            float h = og*tanh_fast(creg);
            hs[gm][j] = h;
            size_t bt = (size_t)(b0+gm)*64 + t;
            out[(bt*10 + p)*64 + j] = h;
        }
        __syncthreads();
    }
}

// ------------------------------------------------------------------
extern "C" void kernel_launch(void* const* d_in, const int* in_sizes, int n_in,
                              void* d_out, int out_size)
{
    const float* x    = (const float*)d_in[0];
    const float* Apos = (const float*)d_in[1];
    const float* Aneg = (const float*)d_in[2];
    const float* Wpb  = (const float*)d_in[3];
    const float* bpb  = (const float*)d_in[4];
    const float* Wnb  = (const float*)d_in[5];
    const float* bnb  = (const float*)d_in[6];
    const float* Wpd  = (const float*)d_in[7];
    const float* bpd  = (const float*)d_in[8];
    const float* Wnd  = (const float*)d_in[9];
    const float* bnd  = (const float*)d_in[10];
    const float* Wih  = (const float*)d_in[11];
    const float* Whh  = (const float*)d_in[12];
    const float* bih  = (const float*)d_in[13];
    const float* bhh  = (const float*)d_in[14];
    float* out = (float*)d_out;

    const int nW = 4096 + 7168 + PP*16*256;
    transform_weights<<<(nW + 255)/256, 256>>>(Wpb, Wnb, Wpd, Wnd, Wih);

    sgcn_kernel<<<BT, 256>>>(x, Apos, Aneg, bpb, bnb, bpd, bnd);

    dim3 gg(BT/16, PP);
    gih_kernel<<<gg, 256>>>(bih, bhh);

    lstm_kernel<<<PP*(BG/4), 256>>>(Whh, out);   // 640 blocks
}